// round 2
// baseline (speedup 1.0000x reference)
#include <cuda_runtime.h>
#include <cuda_bf16.h>

// Problem constants (MultiHeadAttention: B=2, S=2048, E=1024, H=16, DH=64, no softmax)
#define B_   2
#define S_   2048
#define E_   1024
#define H_   16
#define DH_  64
#define MTOT (B_ * S_)          // 4096 rows
#define EPS_ 1e-9f
#define SCALE_ 0.125f           // 1/sqrt(DH)

// Scratch (no cudaMalloc allowed): 4 x 16 MB fp32 buffers
__device__ float g_Q[B_ * S_ * E_];
__device__ float g_K[B_ * S_ * E_];
__device__ float g_V[B_ * S_ * E_];
__device__ float g_A[B_ * S_ * E_];

// ---------------------------------------------------------------------------
// C[M,N] = A[M,K] @ W[N,K]^T + bias[N]
// 128x128 block tile, BK=16, 256 threads, 8x8 per-thread microtile.
// Double-buffered smem with register-staged gmem prefetch:
//   load(k0+16)->regs ; compute buf p ; regs->smem buf 1-p ; 1x syncthreads.
// Smem K-major-transposed (As[k][m]) with +4 pad.
// ---------------------------------------------------------------------------
__global__ void __launch_bounds__(256) gemm_bias_kernel(
    const float* __restrict__ A, const float* __restrict__ W,
    const float* __restrict__ bias, float* __restrict__ C,
    int M, int N, int K)
{
    __shared__ float As[2][16][132];
    __shared__ float Bs[2][16][132];

    const int tid = threadIdx.x;
    const int tx  = tid & 15;        // 0..15 -> n microtile
    const int ty  = tid >> 4;        // 0..15 -> m microtile
    const int m0  = blockIdx.y * 128;
    const int n0  = blockIdx.x * 128;

    // Per-thread gmem staging: 2 float4 from A, 2 from W per K-tile
    const int ldrow0 = (tid + 0)   >> 2;          // 0..63
    const int ldrow1 = (tid + 256) >> 2;          // 64..127
    const int ldkc   = (tid & 3) << 2;            // 0,4,8,12

    const float* Aptr0 = A + (size_t)(m0 + ldrow0) * K + ldkc;
    const float* Aptr1 = A + (size_t)(m0 + ldrow1) * K + ldkc;
    const float* Wptr0 = W + (size_t)(n0 + ldrow0) * K + ldkc;
    const float* Wptr1 = W + (size_t)(n0 + ldrow1) * K + ldkc;

    float4 pa0, pa1, pb0, pb1;

    float acc[8][8];
#pragma unroll
    for (int i = 0; i < 8; ++i)
#pragma unroll
        for (int j = 0; j < 8; ++j) acc[i][j] = 0.0f;

    // Prologue: fill buffer 0
    pa0 = *(const float4*)(Aptr0);
    pa1 = *(const float4*)(Aptr1);
    pb0 = *(const float4*)(Wptr0);
    pb1 = *(const float4*)(Wptr1);
    {
        As[0][ldkc + 0][ldrow0] = pa0.x; As[0][ldkc + 1][ldrow0] = pa0.y;
        As[0][ldkc + 2][ldrow0] = pa0.z; As[0][ldkc + 3][ldrow0] = pa0.w;
        As[0][ldkc + 0][ldrow1] = pa1.x; As[0][ldkc + 1][ldrow1] = pa1.y;
        As[0][ldkc + 2][ldrow1] = pa1.z; As[0][ldkc + 3][ldrow1] = pa1.w;
        Bs[0][ldkc + 0][ldrow0] = pb0.x; Bs[0][ldkc + 1][ldrow0] = pb0.y;
        Bs[0][ldkc + 2][ldrow0] = pb0.z; Bs[0][ldkc + 3][ldrow0] = pb0.w;
        Bs[0][ldkc + 0][ldrow1] = pb1.x; Bs[0][ldkc + 1][ldrow1] = pb1.y;
        Bs[0][ldkc + 2][ldrow1] = pb1.z; Bs[0][ldkc + 3][ldrow1] = pb1.w;
    }
    __syncthreads();

    int p = 0;
    for (int k0 = 0; k0 < K; k0 += 16) {
        const bool has_next = (k0 + 16) < K;
        if (has_next) {
            // Issue next-tile gmem loads early; latency hidden behind compute
            pa0 = *(const float4*)(Aptr0 + k0 + 16);
            pa1 = *(const float4*)(Aptr1 + k0 + 16);
            pb0 = *(const float4*)(Wptr0 + k0 + 16);
            pb1 = *(const float4*)(Wptr1 + k0 + 16);
        }

#pragma unroll
        for (int kk = 0; kk < 16; ++kk) {
            float ar[8], br[8];
            *(float4*)&ar[0] = *(const float4*)&As[p][kk][ty * 8];
            *(float4*)&ar[4] = *(const float4*)&As[p][kk][ty * 8 + 4];
            *(float4*)&br[0] = *(const float4*)&Bs[p][kk][tx * 8];
            *(float4*)&br[4] = *(const float4*)&Bs[p][kk][tx * 8 + 4];
#pragma unroll
            for (int i = 0; i < 8; ++i)
#pragma unroll
                for (int j = 0; j < 8; ++j)
                    acc[i][j] = fmaf(ar[i], br[j], acc[i][j]);
        }

        if (has_next) {
            const int q = p ^ 1;
            As[q][ldkc + 0][ldrow0] = pa0.x; As[q][ldkc + 1][ldrow0] = pa0.y;
            As[q][ldkc + 2][ldrow0] = pa0.z; As[q][ldkc + 3][ldrow0] = pa0.w;
            As[q][ldkc + 0][ldrow1] = pa1.x; As[q][ldkc + 1][ldrow1] = pa1.y;
            As[q][ldkc + 2][ldrow1] = pa1.z; As[q][ldkc + 3][ldrow1] = pa1.w;
            Bs[q][ldkc + 0][ldrow0] = pb0.x; Bs[q][ldkc + 1][ldrow0] = pb0.y;
            Bs[q][ldkc + 2][ldrow0] = pb0.z; Bs[q][ldkc + 3][ldrow0] = pb0.w;
            Bs[q][ldkc + 0][ldrow1] = pb1.x; Bs[q][ldkc + 1][ldrow1] = pb1.y;
            Bs[q][ldkc + 2][ldrow1] = pb1.z; Bs[q][ldkc + 3][ldrow1] = pb1.w;
            __syncthreads();
            p = q;
        }
    }

    // Epilogue: add bias, vectorized store
#pragma unroll
    for (int i = 0; i < 8; ++i) {
        int m = m0 + ty * 8 + i;
#pragma unroll
        for (int jc = 0; jc < 8; jc += 4) {
            int n = n0 + tx * 8 + jc;
            float4 o;
            o.x = acc[i][jc + 0] + bias[n + 0];
            o.y = acc[i][jc + 1] + bias[n + 1];
            o.z = acc[i][jc + 2] + bias[n + 2];
            o.w = acc[i][jc + 3] + bias[n + 3];
            *(float4*)(C + (size_t)m * N + n) = o;
        }
    }
}

// ---------------------------------------------------------------------------
// Fused linear attention (NO softmax):
//   O[b,h,q,:] = sum_k s(q,k) * V[b,h,k,:],  s = mask ? (q.k)/8 : 1e-9
// One block per (q-tile of 64, h, b). Per k-tile: S-tile in regs -> smem
// (reusing the K buffer) -> accumulate O.
// Smem: Qst[d][q] (loaded once), KSs = K^T [d][k] then scores [q][k],
// Vs natural [k][d]. Stride 64 everywhere => 48 KB static.
// Thread owns q = ty*4+i, and k (resp. d) = tx + 16*j.
// ---------------------------------------------------------------------------
__global__ void __launch_bounds__(256) attn_kernel(
    const float* __restrict__ Q, const float* __restrict__ Kp,
    const float* __restrict__ Vp, const int* __restrict__ mask,
    float* __restrict__ O)
{
    __shared__ float Qst[64 * 64];   // [d][q]
    __shared__ float KSs[64 * 64];   // phase A: K^T [d][k]; phase B: scores [q][k]
    __shared__ float Vs [64 * 64];   // [k][d]

    const int b  = blockIdx.z;
    const int h  = blockIdx.y;
    const int q0 = blockIdx.x * 64;
    const int tid = threadIdx.x;
    const int tx  = tid & 15;
    const int ty  = tid >> 4;

    // Load Q tile, transposed into Qst[d][q]
    {
        const float* Qb = Q + ((size_t)(b * S_ + q0)) * E_ + h * DH_;
#pragma unroll
        for (int it = 0; it < 4; ++it) {
            int idx = tid + it * 256;    // 0..1023
            int row = idx >> 4;          // q row 0..63
            int dc  = (idx & 15) << 2;   // d chunk
            float4 v = *(const float4*)(Qb + (size_t)row * E_ + dc);
            Qst[(dc + 0) * 64 + row] = v.x;
            Qst[(dc + 1) * 64 + row] = v.y;
            Qst[(dc + 2) * 64 + row] = v.z;
            Qst[(dc + 3) * 64 + row] = v.w;
        }
    }

    float oacc[4][4];                 // [i][j2]: q = ty*4+i, d = tx + 16*j2
#pragma unroll
    for (int i = 0; i < 4; ++i)
#pragma unroll
        for (int j = 0; j < 4; ++j) oacc[i][j] = 0.0f;

    const int* mbase = mask + (size_t)b * S_ * S_ + (size_t)q0 * S_;

    for (int kt = 0; kt < S_; kt += 64) {
        __syncthreads();   // previous tile's consumers done before overwriting smem

        // Load K (transposed -> KSs[d][k]) and V (natural -> Vs[k][d])
        const float* Kb = Kp + ((size_t)(b * S_ + kt)) * E_ + h * DH_;
        const float* Vb = Vp + ((size_t)(b * S_ + kt)) * E_ + h * DH_;
#pragma unroll
        for (int it = 0; it < 4; ++it) {
            int idx = tid + it * 256;
            int row = idx >> 4;
            int dc  = (idx & 15) << 2;
            float4 kv = *(const float4*)(Kb + (size_t)row * E_ + dc);
            KSs[(dc + 0) * 64 + row] = kv.x;
            KSs[(dc + 1) * 64 + row] = kv.y;
            KSs[(dc + 2) * 64 + row] = kv.z;
            KSs[(dc + 3) * 64 + row] = kv.w;
            float4 vv = *(const float4*)(Vb + (size_t)row * E_ + dc);
            *(float4*)&Vs[row * 64 + dc] = vv;
        }
        __syncthreads();

        // S = Q @ K^T for this tile: s[i][j], k = tx + 16*j
        float s[4][4];
#pragma unroll
        for (int i = 0; i < 4; ++i)
#pragma unroll
            for (int j = 0; j < 4; ++j) s[i][j] = 0.0f;

#pragma unroll 8
        for (int d = 0; d < 64; ++d) {
            float qr[4], kr[4];
#pragma unroll
            for (int i = 0; i < 4; ++i) qr[i] = Qst[d * 64 + ty * 4 + i];
#pragma unroll
            for (int j = 0; j < 4; ++j) kr[j] = KSs[d * 64 + tx + 16 * j];
#pragma unroll
            for (int i = 0; i < 4; ++i)
#pragma unroll
                for (int j = 0; j < 4; ++j)
                    s[i][j] = fmaf(qr[i], kr[j], s[i][j]);
        }

        // Mask + scale (masked -> EPS, per reference; no softmax)
        float sv[4][4];
#pragma unroll
        for (int i = 0; i < 4; ++i)
#pragma unroll
            for (int j = 0; j < 4; ++j) {
                int m = mbase[(size_t)(ty * 4 + i) * S_ + kt + tx + 16 * j];
                sv[i][j] = m ? s[i][j] * SCALE_ : EPS_;
            }

        __syncthreads();   // all K reads complete before overwriting KSs with scores
#pragma unroll
        for (int i = 0; i < 4; ++i)
#pragma unroll
            for (int j = 0; j < 4; ++j)
                KSs[(ty * 4 + i) * 64 + tx + 16 * j] = sv[i][j];
        __syncthreads();

        // O += S @ V
#pragma unroll 8
        for (int k = 0; k < 64; ++k) {
            float vv[4];
#pragma unroll
            for (int j2 = 0; j2 < 4; ++j2) vv[j2] = Vs[k * 64 + tx + 16 * j2];
#pragma unroll
            for (int i = 0; i < 4; ++i) {
                float ss = KSs[(ty * 4 + i) * 64 + k];
#pragma unroll
                for (int j2 = 0; j2 < 4; ++j2)
                    oacc[i][j2] = fmaf(ss, vv[j2], oacc[i][j2]);
            }
        }
    }

    // Store O tile back to [B,S,E] layout (heads interleaved in E)
    float* Ob = O + ((size_t)(b * S_ + q0)) * E_ + h * DH_;
#pragma unroll
    for (int i = 0; i < 4; ++i)
#pragma unroll
        for (int j2 = 0; j2 < 4; ++j2)
            Ob[(size_t)(ty * 4 + i) * E_ + tx + 16 * j2] = oacc[i][j2];
}

// ---------------------------------------------------------------------------
extern "C" void kernel_launch(void* const* d_in, const int* in_sizes, int n_in,
                              void* d_out, int out_size)
{
    const float* query = (const float*)d_in[0];
    const float* key   = (const float*)d_in[1];
    const float* value = (const float*)d_in[2];
    const int*   mask  = (const int*)  d_in[3];
    const float* Wq    = (const float*)d_in[4];
    const float* bq    = (const float*)d_in[5];
    const float* Wk    = (const float*)d_in[6];
    const float* bk    = (const float*)d_in[7];
    const float* Wv    = (const float*)d_in[8];
    const float* bv    = (const float*)d_in[9];
    const float* Wo    = (const float*)d_in[10];
    const float* bo    = (const float*)d_in[11];
    float* out = (float*)d_out;

    float *gq, *gk, *gv, *ga;
    cudaGetSymbolAddress((void**)&gq, g_Q);
    cudaGetSymbolAddress((void**)&gk, g_K);
    cudaGetSymbolAddress((void**)&gv, g_V);
    cudaGetSymbolAddress((void**)&ga, g_A);

    dim3 gblk(256);
    dim3 ggrid(E_ / 128, MTOT / 128);   // (8, 32)

    // Projections: X @ W^T + b
    gemm_bias_kernel<<<ggrid, gblk>>>(query, Wq, bq, gq, MTOT, E_, E_);
    gemm_bias_kernel<<<ggrid, gblk>>>(key,   Wk, bk, gk, MTOT, E_, E_);
    gemm_bias_kernel<<<ggrid, gblk>>>(value, Wv, bv, gv, MTOT, E_, E_);

    // Fused masked linear attention
    dim3 agrid(S_ / 64, H_, B_);        // (32, 16, 2)
    attn_kernel<<<agrid, dim3(256)>>>(gq, gk, gv, mask, ga);

    // Output projection into d_out
    gemm_bias_kernel<<<ggrid, gblk>>>(ga, Wo, bo, out, MTOT, E_, E_);
}